// round 7
// baseline (speedup 1.0000x reference)
#include <cuda_runtime.h>
#include <math.h>

#define N 512
#define C 157
#define M 20
#define NC (N*C)
#define SIGMA2_INV (1.0f/(2.0f*300.0f*300.0f))
#define EPSV 1e-7f
#define INV_DECAY (1.0f/0.9f)
#define LOG2_INV_DECAY 0.15200309344504997f   /* log2(1/0.9) */
#define RPAD 33                                /* rowpart pitch (conflict-free) */
#define NW 12                                  /* warps per CTA */
#define NT (NW*32)                             /* 384 threads */

__device__ float g_partial[N];
__device__ unsigned int g_count = 0;

__global__ __launch_bounds__(NT, 3) void fused_kernel(
    const float* __restrict__ a, const float* __restrict__ aa,
    const float* __restrict__ target, const float* __restrict__ bank_values,
    const int* __restrict__ bank_times, const int* __restrict__ bank_mask,
    const int* __restrict__ ids, const int* __restrict__ times,
    float* __restrict__ out, int out_size)
{
    __shared__ float msg_s[C], fmsg_s[C];
    __shared__ float rowpart[C * RPAD];     // [row][lane]
    __shared__ float colpart[NW][160];      // per-warp col partials
    __shared__ float wpast_w[NW][M], wfut_w[NW][M];  // per-warp weight copies
    __shared__ float wsum[NW];
    __shared__ int last_s;

    const int n = blockIdx.x;
    const int t = threadIdx.x;
    const int w = t >> 5;
    const int l = t & 31;
    const int id = ids[n];
    const float* aa_g = aa + (size_t)n * (C*C);

    // ---- prefetch bank_values row + a/target into registers (no barrier above) ----
    float v[M];
    float av = 0.f, tg = 0.f;
    if (t < C) {
        const float* vals = bank_values + (size_t)id * (M*C);
        #pragma unroll
        for (int m = 0; m < M; m++) v[m] = vals[m*C + t];
        av = a[n*C + t];
        tg = target[n*C + t];
    }

    // ---- temporal weights: EVERY warp computes redundantly (no block barrier) ----
    float denp, denf;
    {
        const bool vd = l < M;
        int tsi = 0, mk = 0;
        if (vd) { tsi = bank_times[id*M + l]; mk = bank_mask[id*M + l]; }  // L1-hot replays
        const float t0 = (float)times[n];
        float ts = (float)tsi;
        float d = ts - t0;
        float kern = __expf(-d*d*SIGMA2_INV);
        bool condp = vd && mk && (ts < t0);
        bool condf = vd && mk && (ts > t0);
        unsigned bp = __ballot_sync(0xFFFFFFFFu, condp);
        unsigned bf = __ballot_sync(0xFFFFFFFFu, condf);
        unsigned below = (1u << l) - 1u;
        float dwp = condp ? exp2f(LOG2_INV_DECAY * (float)__popc(bp & below)) : 0.f;
        float dwf = condf ? exp2f(LOG2_INV_DECAY * (float)__popc(bf & below)) : 0.f;
        if (vd) { wpast_w[w][l] = dwp * kern; wfut_w[w][l] = dwf * kern; }
        // den: geometric series, warp-uniform registers (ballot is uniform)
        float cp_ = (float)__popc(bp), cf_ = (float)__popc(bf);
        denp = (exp2f(LOG2_INV_DECAY * cp_) - 1.f) / (INV_DECAY - 1.f);
        denf = (exp2f(LOG2_INV_DECAY * cf_) - 1.f) / (INV_DECAY - 1.f);
    }
    __syncwarp();

    // ---- msg/fmsg from registers + this warp's weight copy ----
    if (t < C) {
        float nump = 0.f, numf = 0.f;
        #pragma unroll
        for (int m = 0; m < M; m++) {
            nump = fmaf(wpast_w[w][m], v[m], nump);
            numf = fmaf(wfut_w[w][m],  v[m], numf);
        }
        msg_s[t]  = (denp > 0.f) ? nump / fmaxf(denp, EPSV) : 0.f;
        fmsg_s[t] = (denf > 0.f) ? numf / fmaxf(denf, EPSV) : 0.f;
    }
    __syncthreads();

    // ---- single streaming pass over aa; deep unroll for MLP ----
    // lane l owns cols j = l+32q (q<5); warp w owns rows i = w+NW*r.
    const bool q4ok = (l + 128) < C;
    float fm0 = fmsg_s[l];
    float fm1 = fmsg_s[l + 32];
    float fm2 = fmsg_s[l + 64];
    float fm3 = fmsg_s[l + 96];
    float fm4 = q4ok ? fmsg_s[l + 128] : 0.f;
    float c0 = 0.f, c1 = 0.f, c2 = 0.f, c3 = 0.f, c4 = 0.f;

    #pragma unroll 4
    for (int r = 0; r < 14; r++) {
        int i = w + NW*r;
        if (i < C) {
            const float* rp = aa_g + i*C;
            float v0 = rp[l];
            float v1 = rp[l + 32];
            float v2 = rp[l + 64];
            float v3 = rp[l + 96];
            float v4 = q4ok ? rp[l + 128] : 0.f;
            float mi = msg_s[i];                 // broadcast LDS
            c0 = fmaf(v0, mi, c0);
            c1 = fmaf(v1, mi, c1);
            c2 = fmaf(v2, mi, c2);
            c3 = fmaf(v3, mi, c3);
            c4 = fmaf(v4, mi, c4);
            float rs = fmaf(v0, fm0, v1*fm1) + fmaf(v2, fm2, v3*fm3) + v4*fm4;
            rowpart[i*RPAD + l] = rs;
        }
    }
    colpart[w][l]       = c0;
    colpart[w][l + 32]  = c1;
    colpart[w][l + 64]  = c2;
    colpart[w][l + 96]  = c3;
    if (q4ok) colpart[w][l + 128] = c4;
    __syncthreads();

    // ---- epilogue: fold partials, qa, fused double-BCE (fast-math) ----
    float s = 0.f;
    if (t < C) {
        float col = 0.f;
        #pragma unroll
        for (int ww = 0; ww < NW; ww++) col += colpart[ww][t];
        float r0 = 0.f, r1 = 0.f, r2 = 0.f, r3 = 0.f;
        const float* rp = rowpart + t*RPAD;
        #pragma unroll
        for (int j = 0; j < 32; j += 4) {
            r0 += rp[j]; r1 += rp[j+1]; r2 += rp[j+2]; r3 += rp[j+3];
        }
        float x = av + col + ((r0 + r1) + (r2 + r3));
        float qa = 1.f / (1.f + __expf(-x));
        out[n*C + t] = qa;
        float p1 = fminf(fmaxf(qa, EPSV), 1.f - EPSV);
        s  = tg*__logf(p1) + (1.f - tg)*__logf(1.f - p1);
        float p2 = 1.f / (1.f + __expf(-av));
        p2 = fminf(fmaxf(p2, EPSV), 1.f - EPSV);
        s += tg*__logf(p2) + (1.f - tg)*__logf(1.f - p2);
    }
    #pragma unroll
    for (int off = 16; off > 0; off >>= 1)
        s += __shfl_xor_sync(0xFFFFFFFFu, s, off);
    if (l == 0) wsum[w] = s;
    __syncthreads();
    if (t == 0) {
        float bs = 0.f;
        #pragma unroll
        for (int ww = 0; ww < NW; ww++) bs += wsum[ww];
        g_partial[n] = bs;
        __threadfence();
        unsigned old = atomicAdd(&g_count, 1u);
        last_s = (old == N - 1);
    }
    __syncthreads();

    // ---- last CTA folds the 512 partials (deterministic fixed order) ----
    if (last_s) {
        float ps = 0.f;
        if (t < 128)
            ps = (g_partial[t] + g_partial[t + 128])
               + (g_partial[t + 256] + g_partial[t + 384]);
        #pragma unroll
        for (int off = 16; off > 0; off >>= 1)
            ps += __shfl_xor_sync(0xFFFFFFFFu, ps, off);
        if (l == 0) wsum[w] = ps;
        __syncthreads();
        if (t == 0) {
            float tot = ((wsum[0] + wsum[1]) + (wsum[2] + wsum[3]));
            if (out_size > NC) out[NC] = -tot / (3.0f * (float)NC);
            g_count = 0;        // reset for next graph replay
        }
    }
}

extern "C" void kernel_launch(void* const* d_in, const int* in_sizes, int n_in,
                              void* d_out, int out_size) {
    const float* a           = (const float*)d_in[0];
    const float* aa          = (const float*)d_in[1];
    const float* target      = (const float*)d_in[2];
    const float* bank_values = (const float*)d_in[3];
    const int*   bank_times  = (const int*)d_in[4];
    const int*   bank_mask   = (const int*)d_in[5];
    const int*   ids         = (const int*)d_in[6];
    const int*   times       = (const int*)d_in[7];
    float* out = (float*)d_out;

    fused_kernel<<<N, NT>>>(a, aa, target, bank_values, bank_times,
                            bank_mask, ids, times, out, out_size);
}

// round 8
// speedup vs baseline: 1.1577x; 1.1577x over previous
#include <cuda_runtime.h>
#include <math.h>
#include <stdint.h>

#define N 512
#define C 157
#define M 20
#define NC (N*C)
#define SIGMA2_INV (1.0f/(2.0f*300.0f*300.0f))
#define EPSV 1e-7f
#define INV_DECAY (1.0f/0.9f)
#define LOG2_INV_DECAY 0.15200309344504997f   /* log2(1/0.9) */
#define RPAD 33                                /* rowpart pitch (conflict-free) */
#define NW 12                                  /* warps per CTA */
#define NT (NW*32)                             /* 384 threads */

__device__ float g_partial[N];
__device__ unsigned int g_count = 0;

__device__ __forceinline__ void prefetch_l2_bulk(const void* g, unsigned bytes) {
    asm volatile("cp.async.bulk.prefetch.L2.global [%0], %1;\n"
                 :: "l"(g), "r"(bytes));
}

__global__ __launch_bounds__(NT, 4) void fused_kernel(
    const float* __restrict__ a, const float* __restrict__ aa,
    const float* __restrict__ target, const float* __restrict__ bank_values,
    const int* __restrict__ bank_times, const int* __restrict__ bank_mask,
    const int* __restrict__ ids, const int* __restrict__ times,
    float* __restrict__ out, int out_size)
{
    __shared__ float msg_s[C], fmsg_s[C];
    __shared__ float rowpart[C * RPAD];     // [row][lane]
    __shared__ float colpart[NW][160];      // per-warp col partials
    __shared__ float wpast[M], wfut[M];
    __shared__ float denp_s, denf_s;
    __shared__ float wsum[NW];
    __shared__ int last_s;

    const int n = blockIdx.x;
    const int t = threadIdx.x;
    const int w = t >> 5;
    const int l = t & 31;
    const int id = ids[n];
    const float* aa_g = aa + (size_t)n * (C*C);

    // ---- L2 bulk prefetch: whole aa tile + bank row, issued before anything ----
    if (t == 0) {
        uintptr_t p  = (uintptr_t)aa_g;
        uintptr_t p0 = p & ~(uintptr_t)15;                       // 16B-align down
        unsigned  sz = (unsigned)(((p + (size_t)C*C*4) - p0) & ~(uintptr_t)15);
        prefetch_l2_bulk((const void*)p0, sz);
        prefetch_l2_bulk(bank_values + (size_t)id * (M*C), M*C*4);  // 12560B, 16B-aligned
    }

    // ---- prefetch bank_values row + a/target into registers (before any barrier) ----
    float v[M];
    float av = 0.f, tg = 0.f;
    if (t < C) {
        const float* vals = bank_values + (size_t)id * (M*C);
        #pragma unroll
        for (int m = 0; m < M; m++) v[m] = vals[m*C + t];
        av = a[n*C + t];
        tg = target[n*C + t];
    }

    // ---- temporal weights: warp 0, ballot-rank ----
    if (t < 32) {
        const bool vd = l < M;
        int tsi = 0, mk = 0;
        if (vd) { tsi = bank_times[id*M + l]; mk = bank_mask[id*M + l]; }
        const float t0 = (float)times[n];
        float ts = (float)tsi;
        float d = ts - t0;
        float kern = __expf(-d*d*SIGMA2_INV);
        bool condp = vd && mk && (ts < t0);
        bool condf = vd && mk && (ts > t0);
        unsigned bp = __ballot_sync(0xFFFFFFFFu, condp);
        unsigned bf = __ballot_sync(0xFFFFFFFFu, condf);
        unsigned below = (1u << l) - 1u;
        float dwp = condp ? exp2f(LOG2_INV_DECAY * (float)__popc(bp & below)) : 0.f;
        float dwf = condf ? exp2f(LOG2_INV_DECAY * (float)__popc(bf & below)) : 0.f;
        if (vd) { wpast[l] = dwp * kern; wfut[l] = dwf * kern; }
        if (l == 0) {
            float cp_ = (float)__popc(bp), cf_ = (float)__popc(bf);
            denp_s = (exp2f(LOG2_INV_DECAY * cp_) - 1.f) / (INV_DECAY - 1.f);
            denf_s = (exp2f(LOG2_INV_DECAY * cf_) - 1.f) / (INV_DECAY - 1.f);
        }
    }
    __syncthreads();

    // ---- msg/fmsg from registers (no LDG behind this barrier) ----
    if (t < C) {
        float nump = 0.f, numf = 0.f;
        #pragma unroll
        for (int m = 0; m < M; m++) {
            nump = fmaf(wpast[m], v[m], nump);
            numf = fmaf(wfut[m],  v[m], numf);
        }
        float denp = denp_s, denf = denf_s;
        msg_s[t]  = (denp > 0.f) ? nump / fmaxf(denp, EPSV) : 0.f;
        fmsg_s[t] = (denf > 0.f) ? numf / fmaxf(denf, EPSV) : 0.f;
    }
    __syncthreads();

    // ---- single streaming pass over aa (now mostly L2 hits) ----
    // lane l owns cols j = l+32q (q<5); warp w owns rows i = w+NW*r.
    const bool q4ok = (l + 128) < C;
    float fm0 = fmsg_s[l];
    float fm1 = fmsg_s[l + 32];
    float fm2 = fmsg_s[l + 64];
    float fm3 = fmsg_s[l + 96];
    float fm4 = q4ok ? fmsg_s[l + 128] : 0.f;
    float c0 = 0.f, c1 = 0.f, c2 = 0.f, c3 = 0.f, c4 = 0.f;

    #pragma unroll 2
    for (int r = 0; r < 14; r++) {
        int i = w + NW*r;
        if (i < C) {
            const float* rp = aa_g + i*C;
            float v0 = rp[l];
            float v1 = rp[l + 32];
            float v2 = rp[l + 64];
            float v3 = rp[l + 96];
            float v4 = q4ok ? rp[l + 128] : 0.f;
            float mi = msg_s[i];                 // broadcast LDS
            c0 = fmaf(v0, mi, c0);
            c1 = fmaf(v1, mi, c1);
            c2 = fmaf(v2, mi, c2);
            c3 = fmaf(v3, mi, c3);
            c4 = fmaf(v4, mi, c4);
            float rs = fmaf(v0, fm0, v1*fm1) + fmaf(v2, fm2, v3*fm3) + v4*fm4;
            rowpart[i*RPAD + l] = rs;
        }
    }
    colpart[w][l]       = c0;
    colpart[w][l + 32]  = c1;
    colpart[w][l + 64]  = c2;
    colpart[w][l + 96]  = c3;
    if (q4ok) colpart[w][l + 128] = c4;
    __syncthreads();

    // ---- epilogue: fold partials, qa, fused double-BCE (fast-math) ----
    float s = 0.f;
    if (t < C) {
        float col = 0.f;
        #pragma unroll
        for (int ww = 0; ww < NW; ww++) col += colpart[ww][t];
        float r0 = 0.f, r1 = 0.f, r2 = 0.f, r3 = 0.f;
        const float* rp = rowpart + t*RPAD;
        #pragma unroll
        for (int j = 0; j < 32; j += 4) {
            r0 += rp[j]; r1 += rp[j+1]; r2 += rp[j+2]; r3 += rp[j+3];
        }
        float x = av + col + ((r0 + r1) + (r2 + r3));
        float qa = 1.f / (1.f + __expf(-x));
        out[n*C + t] = qa;
        float p1 = fminf(fmaxf(qa, EPSV), 1.f - EPSV);
        s  = tg*__logf(p1) + (1.f - tg)*__logf(1.f - p1);
        float p2 = 1.f / (1.f + __expf(-av));
        p2 = fminf(fmaxf(p2, EPSV), 1.f - EPSV);
        s += tg*__logf(p2) + (1.f - tg)*__logf(1.f - p2);
    }
    #pragma unroll
    for (int off = 16; off > 0; off >>= 1)
        s += __shfl_xor_sync(0xFFFFFFFFu, s, off);
    if (l == 0) wsum[w] = s;
    __syncthreads();
    if (t == 0) {
        float bs = 0.f;
        #pragma unroll
        for (int ww = 0; ww < NW; ww++) bs += wsum[ww];
        g_partial[n] = bs;
        __threadfence();
        unsigned old = atomicAdd(&g_count, 1u);
        last_s = (old == N - 1);
    }
    __syncthreads();

    // ---- last CTA folds the 512 partials (deterministic fixed order) ----
    if (last_s) {
        float ps = 0.f;
        if (t < 128)
            ps = (g_partial[t] + g_partial[t + 128])
               + (g_partial[t + 256] + g_partial[t + 384]);
        #pragma unroll
        for (int off = 16; off > 0; off >>= 1)
            ps += __shfl_xor_sync(0xFFFFFFFFu, ps, off);
        if (l == 0) wsum[w] = ps;
        __syncthreads();
        if (t == 0) {
            float tot = ((wsum[0] + wsum[1]) + (wsum[2] + wsum[3]));
            if (out_size > NC) out[NC] = -tot / (3.0f * (float)NC);
            g_count = 0;        // reset for next graph replay
        }
    }
}

extern "C" void kernel_launch(void* const* d_in, const int* in_sizes, int n_in,
                              void* d_out, int out_size) {
    const float* a           = (const float*)d_in[0];
    const float* aa          = (const float*)d_in[1];
    const float* target      = (const float*)d_in[2];
    const float* bank_values = (const float*)d_in[3];
    const int*   bank_times  = (const int*)d_in[4];
    const int*   bank_mask   = (const int*)d_in[5];
    const int*   ids         = (const int*)d_in[6];
    const int*   times       = (const int*)d_in[7];
    float* out = (float*)d_out;

    fused_kernel<<<N, NT>>>(a, aa, target, bank_values, bank_times,
                            bank_mask, ids, times, out, out_size);
}